// round 3
// baseline (speedup 1.0000x reference)
#include <cuda_runtime.h>
#include <stdint.h>

// labels[b,l,i] = argmin_j ( tn[b,l,i] - cbn[i,j] )
//              = argmax_j cbn[i,j]            (tn[b,l,i] constant over the argmin axis j)
//              = argmax_j codebook[i,j]       (cbn = positive-scale affine of codebook)
// => output = per-row argmax of the 64x64 codebook, tiled B*L = 16384 times.
//
// R2 post-mortem: rel_err == 1.000000e+00 exactly, with the kernel verifiably
// running and the codebook pointer size-verified -> the checker sees our output
// as ~zero. Hypothesis: __output__ dtype is float32; our raw int32 label writes
// reinterpret as f32 denormals (~1e-44 ~= 0) -> norm rel-err exactly 1.0.
// R3 change: emit the labels as FLOAT values.

static constexpr int QDIM   = 64;                    // codebook is QDIM x QDIM
static constexpr int TOTAL4 = (8 * 2048 * 64) / 4;   // 262144 float4 stores (4 MB)

__global__ __launch_bounds__(256) void bestrq_argmax_bcast_f32_kernel(
    const float* __restrict__ codebook,   // (64, 64) row-major
    float4* __restrict__ out4)            // 262144 float4
{
    __shared__ int    s_lbl[QDIM];
    __shared__ float4 s_pat[QDIM / 4];

    const int t = threadIdx.x;

    // Phase 1: per-row argmax. Thread t (t<64) scans row t.
    // Strict '>' keeps the FIRST maximal index, matching jnp.argmin tie-break
    // on (s - c_j), which is monotone non-increasing in c_j.
    if (t < QDIM) {
        const float* row = codebook + t * QDIM;
        float best = row[0];
        int   bi   = 0;
#pragma unroll
        for (int j = 1; j < QDIM; ++j) {
            float v = row[j];
            if (v > best) { best = v; bi = j; }
        }
        s_lbl[t] = bi;
    }
    __syncthreads();

    // Phase 2: pack the 64-label pattern as FLOATS into 16 float4s.
    if (t < QDIM / 4) {
        s_pat[t] = make_float4((float)s_lbl[4 * t + 0], (float)s_lbl[4 * t + 1],
                               (float)s_lbl[4 * t + 2], (float)s_lbl[4 * t + 3]);
    }
    __syncthreads();

    // Phase 3: stream the tiled pattern. float4 index i covers output elements
    // [4i, 4i+4); label pattern period = 64 elems = 16 float4s -> slot (i & 15).
    for (int i = blockIdx.x * blockDim.x + t; i < TOTAL4; i += gridDim.x * blockDim.x) {
        out4[i] = s_pat[i & 15];
    }
}

extern "C" void kernel_launch(void* const* d_in, const int* in_sizes, int n_in,
                              void* d_out, int out_size)
{
    (void)out_size;

    // Robust codebook selection:
    //   elements mode: x=4194304, W=16384, codebook=4096  -> match 4096
    //   bytes mode:    x=16777216, W=65536, codebook=16384 -> match 16384 iff max ~16MB
    const float* codebook = nullptr;
    int max_sz = 0;
    for (int i = 0; i < n_in; ++i) if (in_sizes[i] > max_sz) max_sz = in_sizes[i];
    for (int i = 0; i < n_in; ++i) {
        if (in_sizes[i] == QDIM * QDIM) codebook = (const float*)d_in[i];
    }
    if (!codebook && max_sz > 8 * 1024 * 1024) {  // bytes convention
        for (int i = 0; i < n_in; ++i) {
            if (in_sizes[i] == QDIM * QDIM * 4) codebook = (const float*)d_in[i];
        }
    }
    if (!codebook) codebook = (const float*)d_in[n_in - 1];  // last-ditch fallback

    float4* out4 = (float4*)d_out;  // float32 labels viewed as float4

    // 1024 blocks x 256 threads = 262144 threads -> exactly one float4 store each.
    bestrq_argmax_bcast_f32_kernel<<<1024, 256>>>(codebook, out4);
}

// round 4
// speedup vs baseline: 2.0623x; 2.0623x over previous
#include <cuda_runtime.h>
#include <stdint.h>

// labels[b,l,i] = argmin_j ( tn[b,l,i] - cbn[i,j] )
//              = argmax_j cbn[i,j]            (tn constant over argmin axis j)
//              = argmax_j codebook[i,j]       (cbn = positive-scale affine of codebook)
// => output (float32) = per-row argmax of the 64x64 codebook, tiled B*L = 16384x.
//
// R3 post-mortem: single-kernel version spent ~100% of its 19.4us in the
// REDUNDANT per-block argmax whose row-scan LDGs were fully uncoalesced
// (32 lines per load -> L1=75.8%). R4: two launches — argmax once (1 block,
// smem-staged, coalesced), then a pure broadcast-store kernel.

static constexpr int QDIM   = 64;
static constexpr int SROW   = 65;                    // +1 pad: LDS scan 2-way max
static constexpr int TOTAL4 = (8 * 2048 * 64) / 4;   // 262144 float4 (4 MB)

__device__ float4 g_pat[QDIM / 4];   // the 64-label pattern as floats

// ---------------- Kernel A: one block computes the 64 row-argmaxes ----------
__global__ __launch_bounds__(256) void bestrq_rowargmax_kernel(
    const float* __restrict__ codebook)   // (64, 64) row-major
{
    __shared__ float s_cb[QDIM * SROW];
    __shared__ int   s_lbl[QDIM];

    const int t = threadIdx.x;

    // Coalesced global load of the full 16 KB codebook into padded smem.
    for (int e = t; e < QDIM * QDIM; e += 256) {
        int r = e >> 6, c = e & 63;
        s_cb[r * SROW + c] = codebook[e];
    }
    __syncthreads();

    // Per-row argmax from smem. Strict '>' keeps the FIRST maximal index,
    // matching jnp.argmin on (s - c_j), monotone non-increasing in c_j.
    if (t < QDIM) {
        const float* row = s_cb + t * SROW;
        float best = row[0];
        int   bi   = 0;
#pragma unroll
        for (int j = 1; j < QDIM; ++j) {
            float v = row[j];
            if (v > best) { best = v; bi = j; }
        }
        s_lbl[t] = bi;
    }
    __syncthreads();

    if (t < QDIM / 4) {
        g_pat[t] = make_float4((float)s_lbl[4 * t + 0], (float)s_lbl[4 * t + 1],
                               (float)s_lbl[4 * t + 2], (float)s_lbl[4 * t + 3]);
    }
}

// ---------------- Kernel B: tile the 64-label pattern across 4 MB -----------
__global__ __launch_bounds__(256) void bestrq_bcast_store_kernel(
    float4* __restrict__ out4)            // 262144 float4
{
    __shared__ float4 s_pat[QDIM / 4];
    const int t = threadIdx.x;

    if (t < QDIM / 4) s_pat[t] = g_pat[t];   // 256 B broadcast load (L2-hit)
    __syncthreads();

    // blockIdx.x*256 is a multiple of 16 -> pattern slot depends only on t.
    out4[blockIdx.x * 256 + t] = s_pat[t & 15];
}

extern "C" void kernel_launch(void* const* d_in, const int* in_sizes, int n_in,
                              void* d_out, int out_size)
{
    (void)out_size;

    // Codebook selection by size (elements: 4096; bytes fallback: 16384).
    const float* codebook = nullptr;
    int max_sz = 0;
    for (int i = 0; i < n_in; ++i) if (in_sizes[i] > max_sz) max_sz = in_sizes[i];
    for (int i = 0; i < n_in; ++i) {
        if (in_sizes[i] == QDIM * QDIM) codebook = (const float*)d_in[i];
    }
    if (!codebook && max_sz > 8 * 1024 * 1024) {
        for (int i = 0; i < n_in; ++i) {
            if (in_sizes[i] == QDIM * QDIM * 4) codebook = (const float*)d_in[i];
        }
    }
    if (!codebook) codebook = (const float*)d_in[n_in - 1];

    float4* out4 = (float4*)d_out;

    bestrq_rowargmax_kernel<<<1, 256>>>(codebook);
    bestrq_bcast_store_kernel<<<TOTAL4 / 256, 256>>>(out4);   // 1024 blocks
}

// round 5
// speedup vs baseline: 3.3776x; 1.6378x over previous
#include <cuda_runtime.h>
#include <stdint.h>

// labels[b,l,i] = argmin_j ( tn[b,l,i] - cbn[i,j] )
//              = argmax_j cbn[i,j]            (tn constant over argmin axis j)
//              = argmax_j codebook[i,j]       (cbn = positive-scale affine of codebook)
// => output (float32) = per-row argmax of the 64x64 codebook, tiled B*L = 16384x.
//
// R4 post-mortem: both kernels were overhead-bound (B: 4MB stores at only 8.6% L2;
// A + launch gap ~5.6us). R5: ONE kernel. Every block recomputes the argmax, but
// COALESCED via smem staging (R3's sin was uncoalesced LDGs, not redundancy:
// 256 blocks x 16KB = 4MB of L2 reads ~ 670 chip-cycles, noise). 4-way split row
// scan shortens the serial compare chain; 4 float4 stores per thread.

static constexpr int QDIM    = 64;
static constexpr int SROW    = 68;                    // 64+4 pad: conflict-free-ish chunked scan
static constexpr int TOTAL4  = (8 * 2048 * 64) / 4;   // 262144 float4 (4 MB)
static constexpr int NBLK    = 256;
static constexpr int PER_THR = TOTAL4 / (NBLK * 256); // 4 float4 per thread

__global__ __launch_bounds__(256) void bestrq_fused_kernel(
    const float* __restrict__ codebook,   // (64, 64) row-major
    float4* __restrict__ out4)            // 262144 float4
{
    __shared__ float  s_cb[QDIM * SROW];
    __shared__ float  s_pm[QDIM * 4];     // partial max  [row*4 + part]
    __shared__ int    s_pi[QDIM * 4];     // partial idx
    __shared__ float4 s_pat[QDIM / 4];

    const int t = threadIdx.x;

    // ---- Coalesced load of the 16 KB codebook into padded smem ----
#pragma unroll
    for (int k = 0; k < 16; ++k) {        // 256 threads x 16 = 4096 elements
        int e = k * 256 + t;
        int r = e >> 6, c = e & 63;
        s_cb[r * SROW + c] = codebook[e];
    }
    __syncthreads();

    // ---- Row argmax, 4 threads per row, 16-element contiguous chunks ----
    // Chunked scan with strict '>' keeps the first maximal index per chunk;
    // in-order merge (part 0..3, strict '>') keeps the global first index,
    // matching jnp.argmin on (s - c_j), monotone non-increasing in c_j.
    {
        int row  = t >> 2;                // 0..63
        int part = t & 3;                 // 0..3
        const float* rp = s_cb + row * SROW + part * 16;
        float best = rp[0];
        int   bi   = part * 16;
#pragma unroll
        for (int j = 1; j < 16; ++j) {
            float v = rp[j];
            if (v > best) { best = v; bi = part * 16 + j; }
        }
        s_pm[t] = best;
        s_pi[t] = bi;
    }
    __syncthreads();

    if (t < QDIM) {                       // merge 4 partials in index order
        float best = s_pm[t * 4];
        int   bi   = s_pi[t * 4];
#pragma unroll
        for (int p = 1; p < 4; ++p) {
            float v = s_pm[t * 4 + p];
            if (v > best) { best = v; bi = s_pi[t * 4 + p]; }
        }
        s_pm[t] = (float)bi;              // reuse as float-label slot
    }
    __syncthreads();

    if (t < QDIM / 4) {
        s_pat[t] = make_float4(s_pm[4 * t + 0], s_pm[4 * t + 1],
                               s_pm[4 * t + 2], s_pm[4 * t + 3]);
    }
    __syncthreads();

    // ---- Tile the pattern: 4 coalesced float4 stores per thread ----
    // Offsets are multiples of 16 float4s (one 64-label period), so the
    // pattern slot depends only on (t & 15).
    const float4 v = s_pat[t & 15];
    const int base = blockIdx.x * (256 * PER_THR) + t;
#pragma unroll
    for (int k = 0; k < PER_THR; ++k) {
        out4[base + k * 256] = v;
    }
}

extern "C" void kernel_launch(void* const* d_in, const int* in_sizes, int n_in,
                              void* d_out, int out_size)
{
    (void)out_size;

    // Codebook selection by size (elements: 4096; bytes fallback: 16384).
    const float* codebook = nullptr;
    int max_sz = 0;
    for (int i = 0; i < n_in; ++i) if (in_sizes[i] > max_sz) max_sz = in_sizes[i];
    for (int i = 0; i < n_in; ++i) {
        if (in_sizes[i] == QDIM * QDIM) codebook = (const float*)d_in[i];
    }
    if (!codebook && max_sz > 8 * 1024 * 1024) {
        for (int i = 0; i < n_in; ++i) {
            if (in_sizes[i] == QDIM * QDIM * 4) codebook = (const float*)d_in[i];
        }
    }
    if (!codebook) codebook = (const float*)d_in[n_in - 1];

    bestrq_fused_kernel<<<NBLK, 256>>>(codebook, (float4*)d_out);
}

// round 6
// speedup vs baseline: 3.4301x; 1.0155x over previous
#include <cuda_runtime.h>
#include <stdint.h>

// labels[b,l,i] = argmin_j ( tn[b,l,i] - cbn[i,j] )
//              = argmax_j cbn[i,j]            (tn constant over argmin axis j)
//              = argmax_j codebook[i,j]       (cbn = positive-scale affine of codebook)
// => output (float32) = per-row argmax of the 64x64 codebook, tiled B*L = 16384x.
//
// R5 post-mortem: latency-bound (all pipes <20%); 256 blocks on 148 SMs put a
// 2nd serial wave on 108 SMs, and the smem-staged scan added 2 syncs + a
// 16-deep serial LDS chain. R6: 128 blocks (one wave), registerized argmax via
// monotone u64 keys + shfl, one __syncthreads before the store stream.

static constexpr int QDIM    = 64;
static constexpr int TOTAL4  = (8 * 2048 * 64) / 4;   // 262144 float4 (4 MB)
static constexpr int NBLK    = 128;                   // <= 148 SMs: single wave
static constexpr int PER_THR = TOTAL4 / (NBLK * 256); // 8 float4 per thread

// Monotone key: order-preserving f32 bits in [63:6], (63-j) in [5:0].
// u64-max => max value; among equal values, larger (63-j) => SMALLER j,
// i.e. first-index tie-break, matching jnp.argmin on (s - c_j).
__device__ __forceinline__ unsigned long long mono_key(float v, int j) {
    uint32_t u = __float_as_uint(v);
    u ^= (uint32_t)((int32_t)u >> 31) | 0x80000000u;   // ordered-uint transform
    return ((unsigned long long)u << 6) | (unsigned long long)(63 - j);
}

__device__ __forceinline__ unsigned long long kmax(unsigned long long a,
                                                   unsigned long long b) {
    return a > b ? a : b;
}

__global__ __launch_bounds__(256) void bestrq_fused2_kernel(
    const float4* __restrict__ cb4,       // codebook (64,64) as 1024 float4
    float4* __restrict__ out4)            // 262144 float4
{
    __shared__ float  s_lbl[QDIM];
    __shared__ float4 s_pat[QDIM / 4];

    const int t    = threadIdx.x;
    const int row  = t >> 2;              // 0..63  (4 threads per row)
    const int part = t & 3;               // 0..3   (16 elements each)

    // ---- Load this thread's 16 row elements (4 independent LDG.128) ----
    const float4* p = cb4 + row * 16 + part * 4;
    float4 a = p[0], b = p[1], c = p[2], d = p[3];

    // ---- In-register argmax over 16 elements via monotone keys ----
    const int bj = part * 16;
    unsigned long long k;
    k =      kmax(kmax(mono_key(a.x, bj + 0), mono_key(a.y, bj + 1)),
                  kmax(mono_key(a.z, bj + 2), mono_key(a.w, bj + 3)));
    k = kmax(k, kmax(kmax(mono_key(b.x, bj + 4), mono_key(b.y, bj + 5)),
                     kmax(mono_key(b.z, bj + 6), mono_key(b.w, bj + 7))));
    k = kmax(k, kmax(kmax(mono_key(c.x, bj + 8), mono_key(c.y, bj + 9)),
                     kmax(mono_key(c.z, bj + 10), mono_key(c.w, bj + 11))));
    k = kmax(k, kmax(kmax(mono_key(d.x, bj + 12), mono_key(d.y, bj + 13)),
                     kmax(mono_key(d.z, bj + 14), mono_key(d.w, bj + 15))));

    // ---- Reduce across the 4 lanes of this row (lanes differ only in 'part') ----
    k = kmax(k, __shfl_xor_sync(0xFFFFFFFFu, k, 1));
    k = kmax(k, __shfl_xor_sync(0xFFFFFFFFu, k, 2));

    if (part == 0) s_lbl[row] = (float)(63 - (int)(k & 63));
    __syncthreads();

    if (t < QDIM / 4) {
        s_pat[t] = make_float4(s_lbl[4 * t + 0], s_lbl[4 * t + 1],
                               s_lbl[4 * t + 2], s_lbl[4 * t + 3]);
    }
    __syncthreads();

    // ---- Tile the 64-label pattern: 8 coalesced float4 stores per thread ----
    // All offsets are multiples of 16 float4s (one pattern period), so the
    // slot depends only on (t & 15).
    const float4 v    = s_pat[t & 15];
    const int    base = blockIdx.x * (256 * PER_THR) + t;
#pragma unroll
    for (int kk = 0; kk < PER_THR; ++kk) {
        out4[base + kk * 256] = v;
    }
}

extern "C" void kernel_launch(void* const* d_in, const int* in_sizes, int n_in,
                              void* d_out, int out_size)
{
    (void)out_size;

    // Codebook selection by size (elements: 4096; bytes fallback: 16384).
    const float* codebook = nullptr;
    int max_sz = 0;
    for (int i = 0; i < n_in; ++i) if (in_sizes[i] > max_sz) max_sz = in_sizes[i];
    for (int i = 0; i < n_in; ++i) {
        if (in_sizes[i] == QDIM * QDIM) codebook = (const float*)d_in[i];
    }
    if (!codebook && max_sz > 8 * 1024 * 1024) {
        for (int i = 0; i < n_in; ++i) {
            if (in_sizes[i] == QDIM * QDIM * 4) codebook = (const float*)d_in[i];
        }
    }
    if (!codebook) codebook = (const float*)d_in[n_in - 1];

    bestrq_fused2_kernel<<<NBLK, 256>>>((const float4*)codebook, (float4*)d_out);
}